// round 8
// baseline (speedup 1.0000x reference)
#include <cuda_runtime.h>
#include <math.h>
#include <stdint.h>

#define Dm 128
#define NMAX 50000
#define EMAX 600000

// -------- scratch (device globals; no allocation in kernel_launch) --------
__device__ float g_Q[NMAX * Dm];
__device__ float g_KV[(size_t)NMAX * 256];   // K in cols 0..127, V in cols 128..255
__device__ float g_wV[NMAX * Dm];
__device__ float g_Z[NMAX * 8];
__device__ float g_cs[Dm];
__device__ float g_css[Dm];
// sorted-edge machinery
__device__ int g_cnt[NMAX];
__device__ int g_off[NMAX];
__device__ int g_srcS[EMAX];
__device__ int g_dstS[EMAX];
__device__ int g_perm[EMAX];

__device__ __forceinline__ float to_tf32(float x) {
    uint32_t u;
    asm("cvt.rna.tf32.f32 %0, %1;" : "=r"(u) : "f"(x));
    return __uint_as_float(u);
}

__device__ __forceinline__ void mma_tf32(float* c, const uint32_t* a, const uint32_t* b) {
    asm volatile(
        "mma.sync.aligned.m16n8k8.row.col.f32.tf32.tf32.f32 "
        "{%0,%1,%2,%3},{%4,%5,%6,%7},{%8,%9},{%0,%1,%2,%3};"
        : "+f"(c[0]), "+f"(c[1]), "+f"(c[2]), "+f"(c[3])
        : "r"(a[0]), "r"(a[1]), "r"(a[2]), "r"(a[3]), "r"(b[0]), "r"(b[1]));
}

__device__ __forceinline__ float4 ldcs4(const float4* p) {
    float4 v;
    asm volatile("ld.global.cs.v4.f32 {%0,%1,%2,%3}, [%4];"
                 : "=f"(v.x), "=f"(v.y), "=f"(v.z), "=f"(v.w) : "l"(p));
    return v;
}

#define AS_STRIDE 36
#define WS_STRIDE 136
#define EH_STRIDE 132

// ============ QKV tf32 GEMM (y=0..2) + accumulator zeroing (y=3) ============
__global__ void __launch_bounds__(256, 2) k_gemm_qkv(const float* __restrict__ A,
                                                     const float* __restrict__ WQ,
                                                     const float* __restrict__ WK,
                                                     const float* __restrict__ WV,
                                                     int M) {
    __shared__ float As[128 * AS_STRIDE];
    __shared__ float Ws[32 * WS_STRIDE];

    int tid = threadIdx.x;

    if (blockIdx.y == 3) {
        float4 z4 = make_float4(0.f, 0.f, 0.f, 0.f);
        int stride = gridDim.x * 256;
        for (int i = blockIdx.x * 256 + tid; i < M * 32; i += stride)
            ((float4*)g_wV)[i] = z4;
        for (int i = blockIdx.x * 256 + tid; i < M * 2; i += stride)
            ((float4*)g_Z)[i] = z4;
        for (int i = blockIdx.x * 256 + tid; i < M; i += stride)
            g_cnt[i] = 0;
        if (blockIdx.x == 0 && tid < 128) { g_cs[tid] = 0.f; g_css[tid] = 0.f; }
        return;
    }

    const float* W = (blockIdx.y == 0) ? WQ : (blockIdx.y == 1) ? WK : WV;
    float* C = (blockIdx.y == 0) ? g_Q : g_KV;
    int cst = (blockIdx.y == 0) ? 128 : 256;
    int coff = (blockIdx.y == 2) ? 128 : 0;

    int lane = tid & 31;
    int wid = tid >> 5;
    int warp_m = wid & 3;
    int warp_n = wid >> 2;
    int qr = lane >> 2;
    int qc = lane & 3;
    long row0 = (long)blockIdx.x * 128;

    float acc[2][8][4];
#pragma unroll
    for (int mt = 0; mt < 2; ++mt)
#pragma unroll
        for (int nt = 0; nt < 8; ++nt)
#pragma unroll
            for (int i = 0; i < 4; ++i) acc[mt][nt][i] = 0.0f;

    const float4* A4 = (const float4*)A;
    const float4* W4 = (const float4*)W;
    const uint32_t* Asu = (const uint32_t*)As;
    const uint32_t* Wsu = (const uint32_t*)Ws;

    for (int kc = 0; kc < 4; ++kc) {
        __syncthreads();
#pragma unroll
        for (int i = 0; i < 4; ++i) {
            int idx = tid + i * 256;
            int r = idx >> 3, c = idx & 7;
            float4 v = (row0 + r < M) ? A4[(row0 + r) * 32 + kc * 8 + c]
                                      : make_float4(0.f, 0.f, 0.f, 0.f);
            v.x = to_tf32(v.x); v.y = to_tf32(v.y);
            v.z = to_tf32(v.z); v.w = to_tf32(v.w);
            *(float4*)&As[r * AS_STRIDE + c * 4] = v;
        }
#pragma unroll
        for (int i = 0; i < 4; ++i) {
            int idx = tid + i * 256;
            int k = idx >> 5, c = idx & 31;
            float4 v = W4[(kc * 32 + k) * 32 + c];
            v.x = to_tf32(v.x); v.y = to_tf32(v.y);
            v.z = to_tf32(v.z); v.w = to_tf32(v.w);
            *(float4*)&Ws[k * WS_STRIDE + c * 4] = v;
        }
        __syncthreads();

#pragma unroll
        for (int ks = 0; ks < 4; ++ks) {
            int k0 = ks * 8;
            uint32_t af[2][4];
#pragma unroll
            for (int mt = 0; mt < 2; ++mt) {
                int rbase = (warp_m * 32 + mt * 16 + qr) * AS_STRIDE;
                af[mt][0] = Asu[rbase + k0 + qc];
                af[mt][1] = Asu[rbase + 8 * AS_STRIDE + k0 + qc];
                af[mt][2] = Asu[rbase + k0 + qc + 4];
                af[mt][3] = Asu[rbase + 8 * AS_STRIDE + k0 + qc + 4];
            }
            uint32_t bf[8][2];
#pragma unroll
            for (int nt = 0; nt < 8; ++nt) {
                int n = warp_n * 64 + nt * 8 + qr;
                bf[nt][0] = Wsu[(k0 + qc) * WS_STRIDE + n];
                bf[nt][1] = Wsu[(k0 + qc + 4) * WS_STRIDE + n];
            }
#pragma unroll
            for (int mt = 0; mt < 2; ++mt)
#pragma unroll
                for (int nt = 0; nt < 8; ++nt)
                    mma_tf32(acc[mt][nt], af[mt], bf[nt]);
        }
    }

#pragma unroll
    for (int mt = 0; mt < 2; ++mt) {
        long r = row0 + warp_m * 32 + mt * 16 + qr;
#pragma unroll
        for (int nt = 0; nt < 8; ++nt) {
            int cc = coff + warp_n * 64 + nt * 8 + 2 * qc;
            if (r < M)
                *(float2*)&C[(size_t)r * cst + cc] = make_float2(acc[mt][nt][0], acc[mt][nt][1]);
            if (r + 8 < M)
                *(float2*)&C[(size_t)(r + 8) * cst + cc] = make_float2(acc[mt][nt][2], acc[mt][nt][3]);
        }
    }
}

// ============ counting sort of edges by dst ============
__global__ void __launch_bounds__(256) k_count(const int* __restrict__ ei, int E) {
    int i = blockIdx.x * 256 + threadIdx.x;
    if (i < E) atomicAdd(&g_cnt[ei[E + i]], 1);
}

__global__ void __launch_bounds__(1024) k_scan(int N) {
    __shared__ int part[1024];
    int tid = threadIdx.x;
    int chunk = (N + 1023) >> 10;
    int start = tid * chunk;
    int end = min(start + chunk, N);
    int s = 0;
    for (int i = start; i < end; ++i) s += g_cnt[i];
    part[tid] = s;
    __syncthreads();
    for (int d = 1; d < 1024; d <<= 1) {
        int v = (tid >= d) ? part[tid - d] : 0;
        __syncthreads();
        part[tid] += v;
        __syncthreads();
    }
    int off = (tid > 0) ? part[tid - 1] : 0;
    for (int i = start; i < end; ++i) { g_off[i] = off; off += g_cnt[i]; }
}

__global__ void __launch_bounds__(256) k_scatter(const int* __restrict__ ei, int E) {
    int i = blockIdx.x * 256 + threadIdx.x;
    if (i < E) {
        int d = ei[E + i];
        int pos = atomicAdd(&g_off[d], 1);
        g_srcS[pos] = ei[i];
        g_dstS[pos] = d;
        g_perm[pos] = i;
    }
}

// ============ Fused Eh GEMM + edge attention over dst-sorted edges ============
__global__ void __launch_bounds__(256, 3) k_eh_edge(const float* __restrict__ A,
                                                    const float* __restrict__ W,
                                                    int E) {
    __shared__ float pool[64 * EH_STRIDE];  // 33.8 KB; unions staging + Eh tile
    __shared__ int sSrc[64];
    __shared__ int sDst[64];
    __shared__ int sPerm[64];
    float* As = pool;
    float* Ws = pool + 64 * AS_STRIDE;
    float* EhS = pool;

    int tid = threadIdx.x;
    int lane = tid & 31;
    int wid = tid >> 5;
    int warp_m = wid & 1;
    int warp_n = wid >> 1;
    int qr = lane >> 2;
    int qc = lane & 3;
    long row0 = (long)blockIdx.x * 64;

    if (tid < 64)        sSrc[tid] = (row0 + tid < E) ? g_srcS[row0 + tid] : 0;
    else if (tid < 128)  sDst[tid - 64] = (row0 + tid - 64 < E) ? g_dstS[row0 + tid - 64] : 0;
    else if (tid < 192)  sPerm[tid - 128] = (row0 + tid - 128 < E) ? g_perm[row0 + tid - 128] : 0;

    float acc[2][4][4];
#pragma unroll
    for (int mt = 0; mt < 2; ++mt)
#pragma unroll
        for (int nt = 0; nt < 4; ++nt)
#pragma unroll
            for (int i = 0; i < 4; ++i) acc[mt][nt][i] = 0.0f;

    const float4* A4 = (const float4*)A;
    const float4* W4 = (const float4*)W;
    const uint32_t* Asu = (const uint32_t*)As;
    const uint32_t* Wsu = (const uint32_t*)Ws;

    for (int kc = 0; kc < 4; ++kc) {
        __syncthreads();   // also makes sPerm visible before first A load
#pragma unroll
        for (int i = 0; i < 2; ++i) {
            int idx = tid + i * 256;
            int r = idx >> 3, c = idx & 7;
            float4 v = (row0 + r < E) ? ldcs4(&A4[(size_t)sPerm[r] * 32 + kc * 8 + c])
                                      : make_float4(0.f, 0.f, 0.f, 0.f);
            v.x = to_tf32(v.x); v.y = to_tf32(v.y);
            v.z = to_tf32(v.z); v.w = to_tf32(v.w);
            *(float4*)&As[r * AS_STRIDE + c * 4] = v;
        }
#pragma unroll
        for (int i = 0; i < 4; ++i) {
            int idx = tid + i * 256;
            int k = idx >> 5, c = idx & 31;
            float4 v = W4[(kc * 32 + k) * 32 + c];
            v.x = to_tf32(v.x); v.y = to_tf32(v.y);
            v.z = to_tf32(v.z); v.w = to_tf32(v.w);
            *(float4*)&Ws[k * WS_STRIDE + c * 4] = v;
        }
        __syncthreads();

#pragma unroll
        for (int ks = 0; ks < 4; ++ks) {
            int k0 = ks * 8;
            uint32_t af[2][4];
#pragma unroll
            for (int mt = 0; mt < 2; ++mt) {
                int rbase = (warp_m * 32 + mt * 16 + qr) * AS_STRIDE;
                af[mt][0] = Asu[rbase + k0 + qc];
                af[mt][1] = Asu[rbase + 8 * AS_STRIDE + k0 + qc];
                af[mt][2] = Asu[rbase + k0 + qc + 4];
                af[mt][3] = Asu[rbase + 8 * AS_STRIDE + k0 + qc + 4];
            }
            uint32_t bf[4][2];
#pragma unroll
            for (int nt = 0; nt < 4; ++nt) {
                int n = warp_n * 32 + nt * 8 + qr;
                bf[nt][0] = Wsu[(k0 + qc) * WS_STRIDE + n];
                bf[nt][1] = Wsu[(k0 + qc + 4) * WS_STRIDE + n];
            }
#pragma unroll
            for (int mt = 0; mt < 2; ++mt)
#pragma unroll
                for (int nt = 0; nt < 4; ++nt)
                    mma_tf32(acc[mt][nt], af[mt], bf[nt]);
        }
    }

    __syncthreads();  // staging dead; overwrite with Eh tile

#pragma unroll
    for (int mt = 0; mt < 2; ++mt) {
        int r = warp_m * 32 + mt * 16 + qr;
#pragma unroll
        for (int nt = 0; nt < 4; ++nt) {
            int cc = warp_n * 32 + nt * 8 + 2 * qc;
            *(float2*)&EhS[r * EH_STRIDE + cc] = make_float2(acc[mt][nt][0], acc[mt][nt][1]);
            *(float2*)&EhS[(r + 8) * EH_STRIDE + cc] = make_float2(acc[mt][nt][2], acc[mt][nt][3]);
        }
    }
    __syncthreads();

    // ---- edge phase: 8 sorted edges per warp; run-accumulate per dst ----
    const float4* Q4 = (const float4*)g_Q;
    const float4* KV4 = (const float4*)g_KV;
    float4* wV4 = (float4*)g_wV;
    int el0 = wid * 8;

    int curDst = -1;
    float4 accW = make_float4(0.f, 0.f, 0.f, 0.f);
    float accZ = 0.f;
    float4 qv = make_float4(0.f, 0.f, 0.f, 0.f);

    if (row0 + 64 <= E) {
        // K/V depth-2 pipeline (dst handled per-run)
        int sN[3];
        float4 k[3], v[3];
#pragma unroll
        for (int j = 0; j < 2; ++j) {
            sN[j] = sSrc[el0 + j];
            k[j] = KV4[(size_t)sN[j] * 64 + lane];
            v[j] = KV4[(size_t)sN[j] * 64 + 32 + lane];
        }
#pragma unroll
        for (int i = 0; i < 8; ++i) {
            int st = i % 3;
            int pf = (i + 2) % 3;
            if (i < 6) {
                int sn = sSrc[el0 + i + 2];
                sN[pf] = sn;
                k[pf] = KV4[(size_t)sn * 64 + lane];
                v[pf] = KV4[(size_t)sn * 64 + 32 + lane];
            }
            int dst = sDst[el0 + i];
            if (dst != curDst) {                      // warp-uniform branch
                if (curDst >= 0) {
                    atomicAdd(wV4 + (size_t)curDst * 32 + lane, accW);
                    if ((lane & 3) == 0) atomicAdd(&g_Z[curDst * 8 + (lane >> 2)], accZ);
                }
                curDst = dst;
                accW = make_float4(0.f, 0.f, 0.f, 0.f);
                accZ = 0.f;
                qv = Q4[(size_t)dst * 32 + lane];
            }
            float4 ev = *(const float4*)&EhS[(el0 + i) * EH_STRIDE + lane * 4];
            float4 kv = k[st], vv = v[st];
            float p = qv.x * kv.x * ev.x + qv.y * kv.y * ev.y +
                      qv.z * kv.z * ev.z + qv.w * kv.w * ev.w;
            p += __shfl_xor_sync(0xffffffffu, p, 1);
            p += __shfl_xor_sync(0xffffffffu, p, 2);
            p = fminf(5.0f, fmaxf(-5.0f, 0.25f * p));
            float sc = __expf(p);
            accW.x += vv.x * sc; accW.y += vv.y * sc;
            accW.z += vv.z * sc; accW.w += vv.w * sc;
            accZ += sc;
        }
    } else {
        for (int i = 0; i < 8; ++i) {
            long e = row0 + el0 + i;
            if (e >= E) break;
            int s = sSrc[el0 + i];
            int dst = sDst[el0 + i];
            if (dst != curDst) {
                if (curDst >= 0) {
                    atomicAdd(wV4 + (size_t)curDst * 32 + lane, accW);
                    if ((lane & 3) == 0) atomicAdd(&g_Z[curDst * 8 + (lane >> 2)], accZ);
                }
                curDst = dst;
                accW = make_float4(0.f, 0.f, 0.f, 0.f);
                accZ = 0.f;
                qv = Q4[(size_t)dst * 32 + lane];
            }
            float4 kv = KV4[(size_t)s * 64 + lane];
            float4 vv = KV4[(size_t)s * 64 + 32 + lane];
            float4 ev = *(const float4*)&EhS[(el0 + i) * EH_STRIDE + lane * 4];
            float p = qv.x * kv.x * ev.x + qv.y * kv.y * ev.y +
                      qv.z * kv.z * ev.z + qv.w * kv.w * ev.w;
            p += __shfl_xor_sync(0xffffffffu, p, 1);
            p += __shfl_xor_sync(0xffffffffu, p, 2);
            p = fminf(5.0f, fmaxf(-5.0f, 0.25f * p));
            float sc = __expf(p);
            accW.x += vv.x * sc; accW.y += vv.y * sc;
            accW.z += vv.z * sc; accW.w += vv.w * sc;
            accZ += sc;
        }
    }
    if (curDst >= 0) {
        atomicAdd(wV4 + (size_t)curDst * 32 + lane, accW);
        if ((lane & 3) == 0) atomicAdd(&g_Z[curDst * 8 + (lane >> 2)], accZ);
    }
}

// -------- h = x + wV/(Z+eps) -> out; column stats (vectorized) --------
__global__ void __launch_bounds__(256) k_resid(const float* __restrict__ x,
                                               float* __restrict__ out, int N) {
    __shared__ float red[8 * 128];
    int tid = threadIdx.x;
    int c4 = tid & 31;
    int w = tid >> 5;
    int h = c4 >> 2;
    int r0 = blockIdx.x * 64;

    const float4* x4 = (const float4*)x;
    const float4* wv4 = (const float4*)g_wV;
    float4* o4 = (float4*)out;

    float4 s4 = make_float4(0.f, 0.f, 0.f, 0.f);
    float4 ss4 = make_float4(0.f, 0.f, 0.f, 0.f);
#pragma unroll
    for (int i = 0; i < 8; ++i) {
        int r = r0 + w + i * 8;
        if (r < N) {
            float zinv = 1.0f / (g_Z[r * 8 + h] + 1e-6f);
            size_t idx = (size_t)r * 32 + c4;
            float4 xv = x4[idx];
            float4 wv = wv4[idx];
            float4 hv = make_float4(xv.x + wv.x * zinv, xv.y + wv.y * zinv,
                                    xv.z + wv.z * zinv, xv.w + wv.w * zinv);
            o4[idx] = hv;
            s4.x += hv.x; s4.y += hv.y; s4.z += hv.z; s4.w += hv.w;
            ss4.x += hv.x * hv.x; ss4.y += hv.y * hv.y;
            ss4.z += hv.z * hv.z; ss4.w += hv.w * hv.w;
        }
    }
    *(float4*)&red[w * 128 + c4 * 4] = s4;
    __syncthreads();
    if (tid < 128) {
        float a = 0.f;
#pragma unroll
        for (int ww = 0; ww < 8; ++ww) a += red[ww * 128 + tid];
        atomicAdd(&g_cs[tid], a);
    }
    __syncthreads();
    *(float4*)&red[w * 128 + c4 * 4] = ss4;
    __syncthreads();
    if (tid < 128) {
        float a = 0.f;
#pragma unroll
        for (int ww = 0; ww < 8; ++ww) a += red[ww * 128 + tid];
        atomicAdd(&g_css[tid], a);
    }
}

// -------- batchnorm apply; stats finalized per-block in smem --------
__global__ void __launch_bounds__(256) k_final(float* __restrict__ out,
                                               const float* __restrict__ gamma,
                                               const float* __restrict__ beta,
                                               int N) {
    __shared__ float sm_scale[128];
    __shared__ float sm_shift[128];
    int tid = threadIdx.x;
    if (tid < 128) {
        float inv = 1.0f / (float)N;
        float mean = g_cs[tid] * inv;
        float var = g_css[tid] * inv - mean * mean;
        float rstd = rsqrtf(var + 1e-5f);
        float sc = rstd * gamma[tid];
        sm_scale[tid] = sc;
        sm_shift[tid] = beta[tid] - mean * sc;
    }
    __syncthreads();

    float4* o4 = (float4*)out;
    int total = N * 32;
#pragma unroll
    for (int j = 0; j < 4; ++j) {
        int idx = blockIdx.x * 1024 + j * 256 + tid;
        if (idx < total) {
            int c4 = (idx & 31) * 4;
            float4 v = o4[idx];
            float4 sc = *(float4*)&sm_scale[c4];
            float4 sh = *(float4*)&sm_shift[c4];
            v.x = v.x * sc.x + sh.x;
            v.y = v.y * sc.y + sh.y;
            v.z = v.z * sc.z + sh.z;
            v.w = v.w * sc.w + sh.w;
            o4[idx] = v;
        }
    }
}

extern "C" void kernel_launch(void* const* d_in, const int* in_sizes, int n_in,
                              void* d_out, int out_size) {
    const float* x     = (const float*)d_in[0];
    const float* eattr = (const float*)d_in[1];
    const float* WQ    = (const float*)d_in[2];
    const float* WK    = (const float*)d_in[3];
    const float* WV    = (const float*)d_in[4];
    const float* WE    = (const float*)d_in[5];
    const float* gamma = (const float*)d_in[6];
    const float* beta  = (const float*)d_in[7];
    const int*   ei    = (const int*)d_in[8];

    int N = in_sizes[0] / Dm;
    int E = in_sizes[1] / Dm;
    float* out = (float*)d_out;

    dim3 gq((N + 127) / 128, 4);     // y=0..2: Q/K/V GEMM, y=3: zeroing (wV,Z,stats,cnt)
    k_gemm_qkv<<<gq, 256>>>(x, WQ, WK, WV, N);

    k_count<<<(E + 255) / 256, 256>>>(ei, E);
    k_scan<<<1, 1024>>>(N);
    k_scatter<<<(E + 255) / 256, 256>>>(ei, E);

    k_eh_edge<<<(E + 63) / 64, 256>>>(eattr, WE, E);

    k_resid<<<(N + 63) / 64, 256>>>(x, out, N);
    k_final<<<(N * 32 + 1023) / 1024, 256>>>(out, gamma, beta, N);
}